// round 1
// baseline (speedup 1.0000x reference)
#include <cuda_runtime.h>
#include <math.h>

#define NA 20000
#define NE 640000
#define DD 128
#define GG 32
#define HH 8
#define NIT 4

// ---------------- device scratch (no allocations allowed) ----------------
__device__ float    g_Wfil[(size_t)NE * DD];   // 327.7 MB, iteration-invariant filter
__device__ float    g_h[NA * DD];
__device__ float    g_Q[NA * DD];
__device__ float    g_K[NA * DD];
__device__ float    g_s[NE * HH];              // scores, then exp(scores - max)
__device__ unsigned g_smax[NA * HH];           // ordered-uint encoded max
__device__ float    g_den[NA * HH];            // softmax denom, then reciprocal
__device__ float    g_msg[NA * DD];

// ordered-uint encoding so atomicMax(unsigned) == float max
__device__ __forceinline__ unsigned fenc(float f) {
    unsigned u = __float_as_uint(f);
    return (u & 0x80000000u) ? ~u : (u | 0x80000000u);
}
__device__ __forceinline__ float fdec(unsigned u) {
    return __uint_as_float((u & 0x80000000u) ? (u & 0x7fffffffu) : ~u);
}

// ---------------- 8x8 register-tile GEMM core ----------------
// 256 threads as 16x16 (tx,ty). Thread owns rows {4ty+i, 64+4ty+i}, cols {4tx+j, 64+4tx+j}.
// A: [128 x K] row-major with leading dim LDA (=132 pad for conflict-free broadcast reads).
// B: [K x 128] row-major, read as float4 (conflict-free).
#define ROW8(i) (((i) < 4) ? (4 * ty + (i)) : (64 + 4 * ty + ((i) - 4)))
#define COL8(j) (((j) < 4) ? (4 * tx + (j)) : (64 + 4 * tx + ((j) - 4)))

template <int K, int LDA>
__device__ __forceinline__ void gemm8x8(const float* __restrict__ A,
                                        const float* __restrict__ B,
                                        int tx, int ty, float acc[8][8]) {
#pragma unroll 4
    for (int k = 0; k < K; k++) {
        float a[8];
#pragma unroll
        for (int i = 0; i < 4; i++) {
            a[i]     = A[(4 * ty + i) * LDA + k];
            a[4 + i] = A[(64 + 4 * ty + i) * LDA + k];
        }
        float4 b0 = *(const float4*)(B + k * 128 + 4 * tx);
        float4 b1 = *(const float4*)(B + k * 128 + 64 + 4 * tx);
        float b[8] = {b0.x, b0.y, b0.z, b0.w, b1.x, b1.y, b1.z, b1.w};
#pragma unroll
        for (int i = 0; i < 8; i++)
#pragma unroll
            for (int j = 0; j < 8; j++)
                acc[i][j] = fmaf(a[i], b[j], acc[i][j]);
    }
}

__device__ __forceinline__ void zero8x8(float acc[8][8]) {
#pragma unroll
    for (int i = 0; i < 8; i++)
#pragma unroll
        for (int j = 0; j < 8; j++) acc[i][j] = 0.f;
}

// ---------------- kernels ----------------

// x = emb[z]
__global__ void k_embed(const float* __restrict__ emb, const int* __restrict__ z,
                        float* __restrict__ x) {
    int i = blockIdx.x * blockDim.x + threadIdx.x;
    if (i < NA * DD) {
        int n = i >> 7, d = i & 127;
        x[i] = emb[z[n] * DD + d];
    }
}

// Wfil[e,:] = (f@Wl + bl + swish(f@W1f+b1f)@W2f + b2f) * C(r)  — 128 edges / block
__global__ __launch_bounds__(256) void k_filter(
    const float* __restrict__ xyz, const int* __restrict__ src, const int* __restrict__ dst,
    const float* __restrict__ Wl, const float* __restrict__ bl,
    const float* __restrict__ W1f, const float* __restrict__ b1f,
    const float* __restrict__ W2f, const float* __restrict__ b2f) {
    extern __shared__ float sm[];
    float* sf  = sm;                  // 128*33
    float* sg  = sf + 128 * 33;       // 128*132
    float* sW1 = sg + 128 * 132;      // 32*128
    float* sWl = sW1 + 32 * 128;      // 32*128
    float* sW2 = sWl + 32 * 128;      // 128*128
    float* sr  = sW2 + 128 * 128;     // 128
    float* sC  = sr + 128;            // 128
    float* sb1 = sC + 128;            // 128
    float* sb  = sb1 + 128;           // 128

    int tid = threadIdx.x, tx = tid & 15, ty = tid >> 4;
    int e0 = blockIdx.x * 128;

    for (int i = tid; i < 32 * 128; i += 256) { sW1[i] = W1f[i]; sWl[i] = Wl[i]; }
    for (int i = tid; i < 128 * 128; i += 256) sW2[i] = W2f[i];
    if (tid < 128) {
        sb1[tid] = b1f[tid];
        sb[tid]  = bl[tid] + b2f[tid];
        int e = e0 + tid;
        int s = src[e], d = dst[e];
        float dx = xyz[3 * s] - xyz[3 * d];
        float dy = xyz[3 * s + 1] - xyz[3 * d + 1];
        float dz = xyz[3 * s + 2] - xyz[3 * d + 2];
        float r = sqrtf(dx * dx + dy * dy + dz * dz + 1e-12f);
        sr[tid] = r;
        sC[tid] = (r < 8.f) ? (0.5f * (cospif(r * 0.125f) + 1.f)) : 0.f;
    }
    __syncthreads();
    {   // gaussian expansion f[128][32]: two threads per edge
        int el = tid >> 1, kb = (tid & 1) * 16;
        float r = sr[el];
#pragma unroll
        for (int q = 0; q < 16; q++) {
            float off = (float)(kb + q) * (8.f / 31.f);
            float u = (r - off) * (31.f / 8.f);
            sf[el * 33 + kb + q] = __expf(-0.5f * u * u);
        }
    }
    __syncthreads();

    float acc[8][8];
    zero8x8(acc);
    gemm8x8<32, 33>(sf, sW1, tx, ty, acc);      // f @ W1f
#pragma unroll
    for (int i = 0; i < 8; i++) {
        int r = ROW8(i);
#pragma unroll
        for (int j = 0; j < 8; j++) {
            int c = COL8(j);
            float v = acc[i][j] + sb1[c];
            sg[r * 132 + c] = v / (1.f + __expf(-v));   // swish
        }
    }
    __syncthreads();

    zero8x8(acc);
    gemm8x8<32, 33>(sf, sWl, tx, ty, acc);      // f @ Wl
    gemm8x8<128, 132>(sg, sW2, tx, ty, acc);    // + g @ W2f
#pragma unroll
    for (int i = 0; i < 8; i++) {
        int r = ROW8(i);
        float Cv = sC[r];
        float* out = g_Wfil + (size_t)(e0 + r) * 128;
#pragma unroll
        for (int j = 0; j < 8; j++) {
            int c = COL8(j);
            out[c] = (acc[i][j] + sb[c]) * Cv;
        }
    }
}

// h = x + te[it]; Q = h@Wq; K = h@Wk  — 128 atom rows / block
__global__ __launch_bounds__(256) void k_hqk(const float* __restrict__ x,
                                             const float* __restrict__ te,
                                             const float* __restrict__ Wq,
                                             const float* __restrict__ Wk, int it) {
    extern __shared__ float sm[];
    float* sh = sm;               // 128*132
    float* sB = sh + 128 * 132;   // 128*128
    int tid = threadIdx.x, tx = tid & 15, ty = tid >> 4;
    int n0 = blockIdx.x * 128;

    for (int i = tid; i < 128 * 128; i += 256) {
        int r = i >> 7, c = i & 127;
        int n = n0 + r;
        float v = 0.f;
        if (n < NA) {
            v = x[n * 128 + c] + te[it * 128 + c];
            g_h[n * 128 + c] = v;
        }
        sh[r * 132 + c] = v;
    }
    for (int i = tid; i < 128 * 128; i += 256) sB[i] = Wq[i];
    __syncthreads();

    float acc[8][8];
    zero8x8(acc);
    gemm8x8<128, 132>(sh, sB, tx, ty, acc);
#pragma unroll
    for (int i = 0; i < 8; i++) {
        int n = n0 + ROW8(i);
        if (n < NA) {
            *(float4*)(g_Q + n * 128 + 4 * tx) = make_float4(acc[i][0], acc[i][1], acc[i][2], acc[i][3]);
            *(float4*)(g_Q + n * 128 + 64 + 4 * tx) = make_float4(acc[i][4], acc[i][5], acc[i][6], acc[i][7]);
        }
    }
    __syncthreads();
    for (int i = tid; i < 128 * 128; i += 256) sB[i] = Wk[i];
    __syncthreads();
    zero8x8(acc);
    gemm8x8<128, 132>(sh, sB, tx, ty, acc);
#pragma unroll
    for (int i = 0; i < 8; i++) {
        int n = n0 + ROW8(i);
        if (n < NA) {
            *(float4*)(g_K + n * 128 + 4 * tx) = make_float4(acc[i][0], acc[i][1], acc[i][2], acc[i][3]);
            *(float4*)(g_K + n * 128 + 64 + 4 * tx) = make_float4(acc[i][4], acc[i][5], acc[i][6], acc[i][7]);
        }
    }
}

// per-edge attention scores + running segment max. one warp per edge.
__global__ void k_s(const int* __restrict__ src, const int* __restrict__ dst) {
    int w = (blockIdx.x * blockDim.x + threadIdx.x) >> 5;
    int lane = threadIdx.x & 31;
    if (w >= NE) return;
    int s = src[w], d = dst[w];
    float4 q = *(const float4*)(g_Q + d * 128 + lane * 4);
    float4 k = *(const float4*)(g_K + s * 128 + lane * 4);
    float p = q.x * k.x + q.y * k.y + q.z * k.z + q.w * k.w;
    p += __shfl_xor_sync(0xffffffffu, p, 1);
    p += __shfl_xor_sync(0xffffffffu, p, 2);
    if ((lane & 3) == 0) {
        int h = lane >> 2;
        float sv = p * 0.25f;                      // 1/sqrt(16)
        g_s[w * 8 + h] = sv;
        atomicMax(&g_smax[d * 8 + h], fenc(sv));
    }
}

// es = exp(s - max); accumulate denom
__global__ void k_es(const int* __restrict__ dst) {
    int i = blockIdx.x * blockDim.x + threadIdx.x;
    if (i >= NE * HH) return;
    int e = i >> 3, h = i & 7;
    int d = dst[e];
    float m = fdec(g_smax[d * 8 + h]);
    float es = __expf(g_s[i] - m);
    g_s[i] = es;
    atomicAdd(&g_den[d * 8 + h], es);
}

__global__ void k_recip() {
    int i = blockIdx.x * blockDim.x + threadIdx.x;
    if (i < NA * HH) g_den[i] = 1.f / (g_den[i] + 1e-12f);
}

// fused: A = h[src] ⊙ Wfil ; v = A @ Wv ; msg[dst] += a ⊙ v  (128 edges / block)
__global__ __launch_bounds__(256) void k_msgv(const int* __restrict__ src,
                                              const int* __restrict__ dst,
                                              const float* __restrict__ Wv) {
    extern __shared__ float sm[];
    float* sA  = sm;                   // 128*132
    float* sB  = sA + 128 * 132;       // 128*128
    float* sAf = sB + 128 * 128;       // 128*8  (attention weights a[e,h])
    int*   sDst = (int*)(sAf + 128 * 8);
    int tid = threadIdx.x, tx = tid & 15, ty = tid >> 4;
    int e0 = blockIdx.x * 128;

    for (int i = tid; i < 128 * 128; i += 256) sB[i] = Wv[i];
    if (tid < 128) {
        int e = e0 + tid;
        int d = dst[e];
        sDst[tid] = d;
#pragma unroll
        for (int h = 0; h < 8; h++) sAf[tid * 8 + h] = g_s[e * 8 + h] * g_den[d * 8 + h];
    }
    {   // A tile load: w = h[src] * Wfil  (two threads per row, 64 cols each)
        int r = tid >> 1, cb = (tid & 1) * 64;
        int e = e0 + r;
        int s = src[e];
        const float4* wf = (const float4*)(g_Wfil + (size_t)e * 128 + cb);
        const float4* hp = (const float4*)(g_h + (size_t)s * 128 + cb);
#pragma unroll
        for (int q = 0; q < 16; q++) {
            float4 w = wf[q], hh = hp[q];
            *(float4*)(sA + r * 132 + cb + q * 4) =
                make_float4(w.x * hh.x, w.y * hh.y, w.z * hh.z, w.w * hh.w);
        }
    }
    __syncthreads();

    float acc[8][8];
    zero8x8(acc);
    gemm8x8<128, 132>(sA, sB, tx, ty, acc);

#pragma unroll
    for (int i = 0; i < 8; i++) {
        int r = ROW8(i);
        int d = sDst[r];
        float a0 = sAf[r * 8 + (tx >> 2)];        // head of cols 4tx..4tx+3
        float a1 = sAf[r * 8 + 4 + (tx >> 2)];    // head of cols 64+4tx..
        float* m = g_msg + (size_t)d * 128;
#pragma unroll
        for (int j = 0; j < 4; j++) {
            atomicAdd(m + 4 * tx + j, acc[i][j] * a0);
            atomicAdd(m + 64 + 4 * tx + j, acc[i][4 + j] * a1);
        }
    }
}

// x += msg @ Wo
__global__ __launch_bounds__(256) void k_out(float* __restrict__ x,
                                             const float* __restrict__ Wo) {
    extern __shared__ float sm[];
    float* sA = sm;               // 128*132
    float* sB = sA + 128 * 132;   // 128*128
    int tid = threadIdx.x, tx = tid & 15, ty = tid >> 4;
    int n0 = blockIdx.x * 128;

    for (int i = tid; i < 128 * 128; i += 256) {
        int r = i >> 7, c = i & 127;
        int n = n0 + r;
        sA[r * 132 + c] = (n < NA) ? g_msg[n * 128 + c] : 0.f;
    }
    for (int i = tid; i < 128 * 128; i += 256) sB[i] = Wo[i];
    __syncthreads();

    float acc[8][8];
    zero8x8(acc);
    gemm8x8<128, 132>(sA, sB, tx, ty, acc);
#pragma unroll
    for (int i = 0; i < 8; i++) {
        int n = n0 + ROW8(i);
        if (n < NA) {
            float4 o0 = *(float4*)(x + n * 128 + 4 * tx);
            float4 o1 = *(float4*)(x + n * 128 + 64 + 4 * tx);
            o0.x += acc[i][0]; o0.y += acc[i][1]; o0.z += acc[i][2]; o0.w += acc[i][3];
            o1.x += acc[i][4]; o1.y += acc[i][5]; o1.z += acc[i][6]; o1.w += acc[i][7];
            *(float4*)(x + n * 128 + 4 * tx) = o0;
            *(float4*)(x + n * 128 + 64 + 4 * tx) = o1;
        }
    }
}

__global__ void k_reset() {
    int i = blockIdx.x * blockDim.x + threadIdx.x;
    if (i < NA * DD) g_msg[i] = 0.f;
    if (i < NA * HH) { g_den[i] = 0.f; g_smax[i] = 0u; }
}

// ---------------- launch ----------------
extern "C" void kernel_launch(void* const* d_in, const int* in_sizes, int n_in,
                              void* d_out, int out_size) {
    const float* xyz = (const float*)d_in[0];
    const float* emb = (const float*)d_in[1];
    const float* te  = (const float*)d_in[2];
    const float* Wl  = (const float*)d_in[3];
    const float* bl  = (const float*)d_in[4];
    const float* W1f = (const float*)d_in[5];
    const float* b1f = (const float*)d_in[6];
    const float* W2f = (const float*)d_in[7];
    const float* b2f = (const float*)d_in[8];
    const float* Wq  = (const float*)d_in[9];
    const float* Wk  = (const float*)d_in[10];
    const float* Wv  = (const float*)d_in[11];
    const float* Wo  = (const float*)d_in[12];
    const int*   z   = (const int*)d_in[13];
    const int*   src = (const int*)d_in[14];
    const int*   dst = (const int*)d_in[15];
    float* x = (float*)d_out;

    const int SM_FILTER = (128 * 33 + 128 * 132 + 2 * 32 * 128 + 128 * 128 + 4 * 128) * 4;
    const int SM_HQK    = (128 * 132 + 128 * 128) * 4;
    const int SM_MSGV   = (128 * 132 + 128 * 128 + 128 * 8 + 128) * 4;
    const int SM_OUT    = (128 * 132 + 128 * 128) * 4;

    cudaFuncSetAttribute(k_filter, cudaFuncAttributeMaxDynamicSharedMemorySize, SM_FILTER);
    cudaFuncSetAttribute(k_hqk,    cudaFuncAttributeMaxDynamicSharedMemorySize, SM_HQK);
    cudaFuncSetAttribute(k_msgv,   cudaFuncAttributeMaxDynamicSharedMemorySize, SM_MSGV);
    cudaFuncSetAttribute(k_out,    cudaFuncAttributeMaxDynamicSharedMemorySize, SM_OUT);

    k_embed<<<(NA * DD + 255) / 256, 256>>>(emb, z, x);
    k_filter<<<NE / 128, 256, SM_FILTER>>>(xyz, src, dst, Wl, bl, W1f, b1f, W2f, b2f);

    const int NBLK = (NA + 127) / 128;   // 157
    for (int it = 0; it < NIT; it++) {
        k_reset<<<(NA * DD + 255) / 256, 256>>>();
        k_hqk<<<NBLK, 256, SM_HQK>>>(x, te, Wq, Wk, it);
        k_s<<<NE / 8, 256>>>(src, dst);
        k_es<<<(NE * HH + 255) / 256, 256>>>(dst);
        k_recip<<<(NA * HH + 255) / 256, 256>>>();
        k_msgv<<<NE / 128, 256, SM_MSGV>>>(src, dst, Wv);
        k_out<<<NBLK, 256, SM_OUT>>>(x, Wo);
    }
}

// round 2
// speedup vs baseline: 1.9757x; 1.9757x over previous
#include <cuda_runtime.h>
#include <math.h>

#define NA 20000
#define NE 640000
#define DD 128
#define GG 32
#define HH 8
#define NIT 4
#define NSM 148

// ---------------- device scratch ----------------
__device__ float    g_Wfil[(size_t)NE * DD];   // compacted: only live edges
__device__ int      g_live[NE];
__device__ int      g_nlive;
__device__ float    g_h[NA * DD];
__device__ float    g_Q[NA * DD];
__device__ float    g_K[NA * DD];
__device__ float    g_s[NE * HH];
__device__ unsigned g_smax[NA * HH];
__device__ float    g_den[NA * HH];
__device__ float    g_msg[NA * DD];

__device__ __forceinline__ unsigned fenc(float f) {
    unsigned u = __float_as_uint(f);
    return (u & 0x80000000u) ? ~u : (u | 0x80000000u);
}
__device__ __forceinline__ float fdec(unsigned u) {
    return __uint_as_float((u & 0x80000000u) ? (u & 0x7fffffffu) : ~u);
}

__device__ __forceinline__ void red_add_v4(float* p, float x, float y, float z, float w) {
    asm volatile("red.global.add.v4.f32 [%0], {%1,%2,%3,%4};"
                 :: "l"(p), "f"(x), "f"(y), "f"(z), "f"(w) : "memory");
}

// ---------------- GEMM core v2: k-chunk 4, float4 A loads ----------------
// 256 threads as 16x16 (tx,ty). Thread owns rows {4ty+i, 64+4ty+i}, cols {4tx+j, 64+4tx+j}.
#define ROW8(i) (((i) < 4) ? (4 * ty + (i)) : (64 + 4 * ty + ((i) - 4)))

template <int K, int LDA>
__device__ __forceinline__ void gemm8x8(const float* __restrict__ A,
                                        const float* __restrict__ B,
                                        int tx, int ty, float acc[8][8]) {
#pragma unroll 2
    for (int kk = 0; kk < K; kk += 4) {
        float av[8][4], bv[4][8];
#pragma unroll
        for (int i = 0; i < 4; i++) {
            *(float4*)av[i]   = *(const float4*)(A + (4 * ty + i) * LDA + kk);
            *(float4*)av[4+i] = *(const float4*)(A + (64 + 4 * ty + i) * LDA + kk);
        }
#pragma unroll
        for (int q = 0; q < 4; q++) {
            *(float4*)(&bv[q][0]) = *(const float4*)(B + (kk + q) * 128 + 4 * tx);
            *(float4*)(&bv[q][4]) = *(const float4*)(B + (kk + q) * 128 + 64 + 4 * tx);
        }
#pragma unroll
        for (int q = 0; q < 4; q++)
#pragma unroll
            for (int i = 0; i < 8; i++)
#pragma unroll
                for (int j = 0; j < 8; j++)
                    acc[i][j] = fmaf(av[i][q], bv[q][j], acc[i][j]);
    }
}

__device__ __forceinline__ void zero8x8(float acc[8][8]) {
#pragma unroll
    for (int i = 0; i < 8; i++)
#pragma unroll
        for (int j = 0; j < 8; j++) acc[i][j] = 0.f;
}

// ---------------- kernels ----------------

__global__ void k_embed(const float* __restrict__ emb, const int* __restrict__ z,
                        float* __restrict__ x) {
    int i = blockIdx.x * blockDim.x + threadIdx.x;
    if (i == 0) g_nlive = 0;
    if (i < NA * DD) {
        int n = i >> 7, d = i & 127;
        x[i] = emb[z[n] * DD + d];
    }
}

// live-edge compaction: r < CUTOFF exactly matches C > 0
__global__ void k_classify(const float* __restrict__ xyz, const int* __restrict__ src,
                           const int* __restrict__ dst) {
    int e = blockIdx.x * blockDim.x + threadIdx.x;
    if (e >= NE) return;
    int s = src[e], d = dst[e];
    float dx = xyz[3 * s]     - xyz[3 * d];
    float dy = xyz[3 * s + 1] - xyz[3 * d + 1];
    float dz = xyz[3 * s + 2] - xyz[3 * d + 2];
    float r = sqrtf(dx * dx + dy * dy + dz * dz + 1e-12f);
    if (r < 8.f) {
        int pos = atomicAdd(&g_nlive, 1);
        g_live[pos] = e;
    }
}

// persistent filter over live edges: Wfil[li,:] = (f@Wl+bl + swish(f@W1f+b1f)@W2f+b2f)*C
__global__ __launch_bounds__(256) void k_filter(
    const float* __restrict__ xyz, const int* __restrict__ src, const int* __restrict__ dst,
    const float* __restrict__ Wl, const float* __restrict__ bl,
    const float* __restrict__ W1f, const float* __restrict__ b1f,
    const float* __restrict__ W2f, const float* __restrict__ b2f) {
    extern __shared__ float sm[];
    float* sf  = sm;                   // 128*36
    float* sg  = sf + 128 * 36;        // 128*132
    float* sW1 = sg + 128 * 132;       // 32*128
    float* sWl = sW1 + 32 * 128;       // 32*128
    float* sW2 = sWl + 32 * 128;       // 128*128
    float* sr  = sW2 + 128 * 128;      // 128
    float* sC  = sr + 128;             // 128
    float* sb1 = sC + 128;             // 128
    float* sb  = sb1 + 128;            // 128

    int tid = threadIdx.x, tx = tid & 15, ty = tid >> 4;

    for (int i = tid; i < 32 * 128; i += 256) { sW1[i] = W1f[i]; sWl[i] = Wl[i]; }
    for (int i = tid; i < 128 * 128; i += 256) sW2[i] = W2f[i];
    if (tid < 128) { sb1[tid] = b1f[tid]; sb[tid] = bl[tid] + b2f[tid]; }

    int nlive = g_nlive;
    for (int t = blockIdx.x; t * 128 < nlive; t += gridDim.x) {
        if (tid < 128) {
            int li = t * 128 + tid;
            float r = 100.f, C = 0.f;
            if (li < nlive) {
                int e = g_live[li];
                int s = src[e], d = dst[e];
                float dx = xyz[3 * s]     - xyz[3 * d];
                float dy = xyz[3 * s + 1] - xyz[3 * d + 1];
                float dz = xyz[3 * s + 2] - xyz[3 * d + 2];
                r = sqrtf(dx * dx + dy * dy + dz * dz + 1e-12f);
                C = (r < 8.f) ? (0.5f * (cospif(r * 0.125f) + 1.f)) : 0.f;
            }
            sr[tid] = r; sC[tid] = C;
        }
        __syncthreads();
        {   // gaussian expansion
            int el = tid >> 1, kb = (tid & 1) * 16;
            float r = sr[el];
#pragma unroll
            for (int q = 0; q < 16; q++) {
                float off = (float)(kb + q) * (8.f / 31.f);
                float u = (r - off) * (31.f / 8.f);
                sf[el * 36 + kb + q] = __expf(-0.5f * u * u);
            }
        }
        __syncthreads();

        float acc[8][8];
        zero8x8(acc);
        gemm8x8<32, 36>(sf, sW1, tx, ty, acc);
#pragma unroll
        for (int i = 0; i < 8; i++) {
            int r = ROW8(i);
#pragma unroll
            for (int j = 0; j < 8; j++) {
                int c = (j < 4) ? (4 * tx + j) : (64 + 4 * tx + j - 4);
                float v = acc[i][j] + sb1[c];
                sg[r * 132 + c] = v / (1.f + __expf(-v));
            }
        }
        __syncthreads();

        zero8x8(acc);
        gemm8x8<32, 36>(sf, sWl, tx, ty, acc);
        gemm8x8<128, 132>(sg, sW2, tx, ty, acc);
#pragma unroll
        for (int i = 0; i < 8; i++) {
            int r = ROW8(i);
            int li = t * 128 + r;
            if (li < nlive) {
                float Cv = sC[r];
                float* out = g_Wfil + (size_t)li * 128;
#pragma unroll
                for (int j = 0; j < 8; j++) {
                    int c = (j < 4) ? (4 * tx + j) : (64 + 4 * tx + j - 4);
                    out[c] = (acc[i][j] + sb[c]) * Cv;
                }
            }
        }
        __syncthreads();
    }
}

// h = x + te[it]; Q = h@Wq; K = h@Wk
__global__ __launch_bounds__(256) void k_hqk(const float* __restrict__ x,
                                             const float* __restrict__ te,
                                             const float* __restrict__ Wq,
                                             const float* __restrict__ Wk, int it) {
    extern __shared__ float sm[];
    float* sh = sm;               // 128*132
    float* sB = sh + 128 * 132;   // 128*128
    int tid = threadIdx.x, tx = tid & 15, ty = tid >> 4;
    int n0 = blockIdx.x * 128;

    for (int i = tid; i < 128 * 128; i += 256) {
        int r = i >> 7, c = i & 127;
        int n = n0 + r;
        float v = 0.f;
        if (n < NA) {
            v = x[n * 128 + c] + te[it * 128 + c];
            g_h[n * 128 + c] = v;
        }
        sh[r * 132 + c] = v;
    }
    for (int i = tid; i < 128 * 128; i += 256) sB[i] = Wq[i];
    __syncthreads();

    float acc[8][8];
    zero8x8(acc);
    gemm8x8<128, 132>(sh, sB, tx, ty, acc);
#pragma unroll
    for (int i = 0; i < 8; i++) {
        int n = n0 + ROW8(i);
        if (n < NA) {
            *(float4*)(g_Q + n * 128 + 4 * tx)      = make_float4(acc[i][0], acc[i][1], acc[i][2], acc[i][3]);
            *(float4*)(g_Q + n * 128 + 64 + 4 * tx) = make_float4(acc[i][4], acc[i][5], acc[i][6], acc[i][7]);
        }
    }
    __syncthreads();
    for (int i = tid; i < 128 * 128; i += 256) sB[i] = Wk[i];
    __syncthreads();
    zero8x8(acc);
    gemm8x8<128, 132>(sh, sB, tx, ty, acc);
#pragma unroll
    for (int i = 0; i < 8; i++) {
        int n = n0 + ROW8(i);
        if (n < NA) {
            *(float4*)(g_K + n * 128 + 4 * tx)      = make_float4(acc[i][0], acc[i][1], acc[i][2], acc[i][3]);
            *(float4*)(g_K + n * 128 + 64 + 4 * tx) = make_float4(acc[i][4], acc[i][5], acc[i][6], acc[i][7]);
        }
    }
}

// per-edge scores + segment max. one warp per edge.
__global__ void k_s(const int* __restrict__ src, const int* __restrict__ dst) {
    int w = (blockIdx.x * blockDim.x + threadIdx.x) >> 5;
    int lane = threadIdx.x & 31;
    if (w >= NE) return;
    int s = src[w], d = dst[w];
    float4 q = *(const float4*)(g_Q + d * 128 + lane * 4);
    float4 k = *(const float4*)(g_K + s * 128 + lane * 4);
    float p = q.x * k.x + q.y * k.y + q.z * k.z + q.w * k.w;
    p += __shfl_xor_sync(0xffffffffu, p, 1);
    p += __shfl_xor_sync(0xffffffffu, p, 2);
    if ((lane & 3) == 0) {
        int h = lane >> 2;
        float sv = p * 0.25f;
        g_s[w * 8 + h] = sv;
        atomicMax(&g_smax[d * 8 + h], fenc(sv));
    }
}

// es = exp(s - max); denom via vector red. one thread per edge.
__global__ void k_es(const int* __restrict__ dst) {
    int e = blockIdx.x * blockDim.x + threadIdx.x;
    if (e >= NE) return;
    int d = dst[e];
    uint4 m0 = *(const uint4*)(g_smax + d * 8);
    uint4 m1 = *(const uint4*)(g_smax + d * 8 + 4);
    float4 s0 = *(const float4*)(g_s + e * 8);
    float4 s1 = *(const float4*)(g_s + e * 8 + 4);
    float4 e0 = make_float4(__expf(s0.x - fdec(m0.x)), __expf(s0.y - fdec(m0.y)),
                            __expf(s0.z - fdec(m0.z)), __expf(s0.w - fdec(m0.w)));
    float4 e1 = make_float4(__expf(s1.x - fdec(m1.x)), __expf(s1.y - fdec(m1.y)),
                            __expf(s1.z - fdec(m1.z)), __expf(s1.w - fdec(m1.w)));
    *(float4*)(g_s + e * 8)     = e0;
    *(float4*)(g_s + e * 8 + 4) = e1;
    red_add_v4(g_den + d * 8,     e0.x, e0.y, e0.z, e0.w);
    red_add_v4(g_den + d * 8 + 4, e1.x, e1.y, e1.z, e1.w);
}

__global__ void k_recip() {
    int i = blockIdx.x * blockDim.x + threadIdx.x;
    if (i < NA * HH) g_den[i] = 1.f / (g_den[i] + 1e-12f);
}

// persistent fused msg: A = h[src] ⊙ Wfil ; v = A @ Wv ; msg[dst] += a ⊙ v
__global__ __launch_bounds__(256) void k_msgv(const int* __restrict__ src,
                                              const int* __restrict__ dst,
                                              const float* __restrict__ Wv) {
    extern __shared__ float sm[];
    float* sA  = sm;                   // 128*132
    float* sB  = sA + 128 * 132;       // 128*128
    float* sAf = sB + 128 * 128;       // 128*8
    int*   sDst = (int*)(sAf + 128 * 8);
    int tid = threadIdx.x, tx = tid & 15, ty = tid >> 4;

    for (int i = tid; i < 128 * 128; i += 256) sB[i] = Wv[i];
    int nlive = g_nlive;

    for (int t = blockIdx.x; t * 128 < nlive; t += gridDim.x) {
        if (tid < 128) {
            int li = t * 128 + tid;
            if (li < nlive) {
                int e = g_live[li];
                int d = dst[e];
                sDst[tid] = d;
                float4 s0 = *(const float4*)(g_s + e * 8);
                float4 s1 = *(const float4*)(g_s + e * 8 + 4);
                float4 d0 = *(const float4*)(g_den + d * 8);
                float4 d1 = *(const float4*)(g_den + d * 8 + 4);
                *(float4*)(sAf + tid * 8)     = make_float4(s0.x * d0.x, s0.y * d0.y, s0.z * d0.z, s0.w * d0.w);
                *(float4*)(sAf + tid * 8 + 4) = make_float4(s1.x * d1.x, s1.y * d1.y, s1.z * d1.z, s1.w * d1.w);
            } else sDst[tid] = -1;
        }
        {
            int r = tid >> 1, cb = (tid & 1) * 64;
            int li = t * 128 + r;
            if (li < nlive) {
                int e = g_live[li];
                int s = src[e];
                const float4* wf = (const float4*)(g_Wfil + (size_t)li * 128 + cb);
                const float4* hp = (const float4*)(g_h + (size_t)s * 128 + cb);
#pragma unroll
                for (int q = 0; q < 16; q++) {
                    float4 w = wf[q], hh = hp[q];
                    *(float4*)(sA + r * 132 + cb + q * 4) =
                        make_float4(w.x * hh.x, w.y * hh.y, w.z * hh.z, w.w * hh.w);
                }
            } else {
#pragma unroll
                for (int q = 0; q < 16; q++)
                    *(float4*)(sA + r * 132 + cb + q * 4) = make_float4(0.f, 0.f, 0.f, 0.f);
            }
        }
        __syncthreads();

        float acc[8][8];
        zero8x8(acc);
        gemm8x8<128, 132>(sA, sB, tx, ty, acc);

#pragma unroll
        for (int i = 0; i < 8; i++) {
            int r = ROW8(i);
            int d = sDst[r];
            if (d >= 0) {
                float a0 = sAf[r * 8 + (tx >> 2)];
                float a1 = sAf[r * 8 + 4 + (tx >> 2)];
                float* m = g_msg + (size_t)d * 128;
                red_add_v4(m + 4 * tx,      acc[i][0] * a0, acc[i][1] * a0, acc[i][2] * a0, acc[i][3] * a0);
                red_add_v4(m + 64 + 4 * tx, acc[i][4] * a1, acc[i][5] * a1, acc[i][6] * a1, acc[i][7] * a1);
            }
        }
        __syncthreads();
    }
}

// x += msg @ Wo
__global__ __launch_bounds__(256) void k_out(float* __restrict__ x,
                                             const float* __restrict__ Wo) {
    extern __shared__ float sm[];
    float* sA = sm;               // 128*132
    float* sB = sA + 128 * 132;   // 128*128
    int tid = threadIdx.x, tx = tid & 15, ty = tid >> 4;
    int n0 = blockIdx.x * 128;

    for (int i = tid; i < 128 * 128; i += 256) {
        int r = i >> 7, c = i & 127;
        int n = n0 + r;
        sA[r * 132 + c] = (n < NA) ? g_msg[n * 128 + c] : 0.f;
    }
    for (int i = tid; i < 128 * 128; i += 256) sB[i] = Wo[i];
    __syncthreads();

    float acc[8][8];
    zero8x8(acc);
    gemm8x8<128, 132>(sA, sB, tx, ty, acc);
#pragma unroll
    for (int i = 0; i < 8; i++) {
        int n = n0 + ROW8(i);
        if (n < NA) {
            float4 o0 = *(float4*)(x + n * 128 + 4 * tx);
            float4 o1 = *(float4*)(x + n * 128 + 64 + 4 * tx);
            o0.x += acc[i][0]; o0.y += acc[i][1]; o0.z += acc[i][2]; o0.w += acc[i][3];
            o1.x += acc[i][4]; o1.y += acc[i][5]; o1.z += acc[i][6]; o1.w += acc[i][7];
            *(float4*)(x + n * 128 + 4 * tx) = o0;
            *(float4*)(x + n * 128 + 64 + 4 * tx) = o1;
        }
    }
}

__global__ void k_reset() {
    int i = blockIdx.x * blockDim.x + threadIdx.x;
    if (i < NA * DD) g_msg[i] = 0.f;
    if (i < NA * HH) { g_den[i] = 0.f; g_smax[i] = 0u; }
}

// ---------------- launch ----------------
extern "C" void kernel_launch(void* const* d_in, const int* in_sizes, int n_in,
                              void* d_out, int out_size) {
    const float* xyz = (const float*)d_in[0];
    const float* emb = (const float*)d_in[1];
    const float* te  = (const float*)d_in[2];
    const float* Wl  = (const float*)d_in[3];
    const float* bl  = (const float*)d_in[4];
    const float* W1f = (const float*)d_in[5];
    const float* b1f = (const float*)d_in[6];
    const float* W2f = (const float*)d_in[7];
    const float* b2f = (const float*)d_in[8];
    const float* Wq  = (const float*)d_in[9];
    const float* Wk  = (const float*)d_in[10];
    const float* Wv  = (const float*)d_in[11];
    const float* Wo  = (const float*)d_in[12];
    const int*   z   = (const int*)d_in[13];
    const int*   src = (const int*)d_in[14];
    const int*   dst = (const int*)d_in[15];
    float* x = (float*)d_out;

    const int SM_FILTER = (128 * 36 + 128 * 132 + 2 * 32 * 128 + 128 * 128 + 4 * 128) * 4;
    const int SM_HQK    = (128 * 132 + 128 * 128) * 4;
    const int SM_MSGV   = (128 * 132 + 128 * 128 + 128 * 8 + 128) * 4;
    const int SM_OUT    = (128 * 132 + 128 * 128) * 4;

    cudaFuncSetAttribute(k_filter, cudaFuncAttributeMaxDynamicSharedMemorySize, SM_FILTER);
    cudaFuncSetAttribute(k_hqk,    cudaFuncAttributeMaxDynamicSharedMemorySize, SM_HQK);
    cudaFuncSetAttribute(k_msgv,   cudaFuncAttributeMaxDynamicSharedMemorySize, SM_MSGV);
    cudaFuncSetAttribute(k_out,    cudaFuncAttributeMaxDynamicSharedMemorySize, SM_OUT);

    k_embed<<<(NA * DD + 255) / 256, 256>>>(emb, z, x);
    k_classify<<<NE / 256, 256>>>(xyz, src, dst);
    k_filter<<<NSM, 256, SM_FILTER>>>(xyz, src, dst, Wl, bl, W1f, b1f, W2f, b2f);

    const int NBLK = (NA + 127) / 128;   // 157
    for (int it = 0; it < NIT; it++) {
        k_reset<<<(NA * DD + 255) / 256, 256>>>();
        k_hqk<<<NBLK, 256, SM_HQK>>>(x, te, Wq, Wk, it);
        k_s<<<NE / 8, 256>>>(src, dst);
        k_es<<<NE / 256, 256>>>(dst);
        k_recip<<<(NA * HH + 255) / 256, 256>>>();
        k_msgv<<<NSM, 256, SM_MSGV>>>(src, dst, Wv);
        k_out<<<NBLK, 256, SM_OUT>>>(x, Wo);
    }
}